// round 15
// baseline (speedup 1.0000x reference)
#include <cuda_runtime.h>
#include <cuda_bf16.h>
#include <float.h>
#include <math.h>

// Problem shape (fixed by reference setup_inputs)
#define B_   16
#define C_   256
#define H_   128
#define W_   128
#define HW_  (H_ * W_)           // 16384
#define HW4_ (HW_ / 4)           // 4096 float4 columns per image

// Scratch: feat [B, 2, H, W]  (avg then max)
__device__ float g_feat[B_ * 2 * HW_];

// MUFU-free sigmoid (R14, current best): all FMA/ALU pipe.
__device__ __forceinline__ float fast_sigmoid(float x)
{
    float y = -x * 1.4426950408889634f;
    y = fminf(fmaxf(y, -126.0f), 126.0f);
    float n = floorf(y);
    float f = y - n;                         // f in [0,1)
    float p = 1.3333558146428443e-3f;
    p = fmaf(p, f, 9.8105352697968360e-3f);
    p = fmaf(p, f, 5.5518340325804030e-2f);
    p = fmaf(p, f, 2.4017933341410937e-1f);
    p = fmaf(p, f, 6.9314692312196549e-1f);
    p = fmaf(p, f, 1.0f);
    const int ni = (int)n;
    const float s = __int_as_float((ni + 127) << 23);   // 2^n
    const float t = s * p;                   // e^(-x)
    const float u = 1.0f + t;
    float r = __uint_as_float(0x7EF311C3u - __float_as_uint(u));
    r = r * (2.0f - u * r);
    r = r * (2.0f - u * r);
    r = r * (2.0f - u * r);
    return r;
}

// ---------------------------------------------------------------------------
// Kernel 1: channel-wise mean + max over C=256.
// Block = full spatial row, 256 thr = (32 float4 cols) x (8 splits of 32 ch)?
// NO — block = (32 cols) x (8 channel-splits of 32 ch) covers one full row
// with 8 loads... Layout: 8192 blocks x 256 thr: quarter... Final geometry:
// block covers one FULL row (32 float4 cols) with 8 channel-splits of 32 ch,
// 8192 blocks = 2 blocks per (row, ch-half): blk bit0 selects channels
// [0,128) or [128,256). Each thread: 16... -> simplest consistent scheme:
// blk -> (row_id, ch_half). Thread = (col 0..31, split 0..7), loads 16
// channels strided. 32KB per block, 8 loads... (16 ch x 1 float4 = 16 loads?
// No: 128 ch / 8 splits = 16 ch per thread.) Wait - to HALVE the quantum at
// 256 threads we halve per-thread loads to 8: block = (32 cols x 8 splits),
// channels per split = 128/8 = 16?? That's 16 loads. Use ch_half of 64:
// 4 blocks per row, 64 ch each, split 8 -> 8 ch per thread = 8 loads. 32KB.
// ---------------------------------------------------------------------------
__global__ __launch_bounds__(256) void reduce_mean_max_kernel(
    const float* __restrict__ x)
{
    cudaTriggerProgrammaticLaunchCompletion();

    __shared__ float4 s_sum[256];
    __shared__ float4 s_max[256];
    // partial cross-block combine buffers in gmem are avoided: 4 blocks per
    // row each own DISTINCT channel ranges, so they cannot combine locally.
    // Instead: block = (row, ch_quarter) reduces its 64 channels fully and
    // atomically... NO atomics. Revert to self-contained: each block owns a
    // half-row and 128 channels? That's 16 loads again.
    //
    // Self-contained finer quantum at 256 thr: block = half-row x half-chan:
    // (16 cols) x (16 splits) over 128 channels = 8 loads/thread, 32 KB.
    // Two blocks per (half-row) pair combine via... they'd write the same
    // feat slot. Avoid cross-block combine: make the pair split SPATIALLY
    // instead: block = quarter-row (8 cols) x 16 splits x 16 ch = 8 loads.
    // Fully self-contained. 8192 blocks x 256 thr.

    const int tid = threadIdx.x;
    const int col = tid & 7;                   // float4 col within quarter-row
    const int cs  = tid >> 3;                  // channel split 0..31

    const int blk  = blockIdx.x;               // 0..8191
    const int b    = blk >> 9;                 // 512 blocks per image
    const int q    = blk & 511;
    const int h    = q >> 2;                   // row
    const int quar = q & 3;                    // quarter within row
    const int hw4  = (h << 5) + (quar << 3) + col;

    const float4* xb = reinterpret_cast<const float4*>(x)
                     + (size_t)b * C_ * HW4_ + (size_t)(cs * 8) * HW4_ + hw4;

    float4 s = make_float4(0.f, 0.f, 0.f, 0.f);
    float4 m = make_float4(-FLT_MAX, -FLT_MAX, -FLT_MAX, -FLT_MAX);

    #pragma unroll
    for (int c = 0; c < 8; ++c) {
        float4 v = __ldcs(xb + (size_t)c * HW4_);
        s.x += v.x; s.y += v.y; s.z += v.z; s.w += v.w;
        m.x = fmaxf(m.x, v.x); m.y = fmaxf(m.y, v.y);
        m.z = fmaxf(m.z, v.z); m.w = fmaxf(m.w, v.w);
    }

    s_sum[tid] = s;
    s_max[tid] = m;
    __syncthreads();

    if (tid < 8) {
        #pragma unroll
        for (int k = 1; k < 32; ++k) {
            float4 ps = s_sum[tid + k * 8];
            float4 pm = s_max[tid + k * 8];
            s.x += ps.x; s.y += ps.y; s.z += ps.z; s.w += ps.w;
            m.x = fmaxf(m.x, pm.x); m.y = fmaxf(m.y, pm.y);
            m.z = fmaxf(m.z, pm.z); m.w = fmaxf(m.w, pm.w);
        }
        const float inv = 1.0f / (float)C_;
        float4 a = make_float4(s.x * inv, s.y * inv, s.z * inv, s.w * inv);

        float4* fa = reinterpret_cast<float4*>(g_feat)
                   + (size_t)b * 2 * HW4_ + hw4;
        fa[0]    = a;   // channel 0: avg
        fa[HW4_] = m;   // channel 1: max
    }
}

// ---------------------------------------------------------------------------
// Kernel 2: 3x3 conv + MUFU-free sigmoid. (R14 best config, byte-identical)
// ---------------------------------------------------------------------------
__global__ __launch_bounds__(256) void conv_sigmoid_kernel(
    const float* __restrict__ conv_w,   // [1,2,3,3] OIHW
    float* __restrict__ out)            // [B,1,H,W]
{
    const int idx = blockIdx.x * blockDim.x + threadIdx.x;  // 0 .. B*HW-1
    const int b  = idx >> 14;
    const int hw = idx & (HW_ - 1);
    const int h  = hw >> 7;
    const int w  = hw & (W_ - 1);

    float wk[18];
    #pragma unroll
    for (int i = 0; i < 18; ++i) wk[i] = __ldg(conv_w + i);

    cudaGridDependencySynchronize();

    const float* f0 = g_feat + (size_t)b * 2 * HW_;
    const float* f1 = f0 + HW_;

    float acc = 0.f;
    #pragma unroll
    for (int kh = 0; kh < 3; ++kh) {
        const int hh = h + kh - 1;
        if (hh < 0 || hh >= H_) continue;
        #pragma unroll
        for (int kw = 0; kw < 3; ++kw) {
            const int ww = w + kw - 1;
            if (ww < 0 || ww >= W_) continue;
            const int off = hh * W_ + ww;
            acc = fmaf(f0[off], wk[kh * 3 + kw], acc);
            acc = fmaf(f1[off], wk[9 + kh * 3 + kw], acc);
        }
    }

    out[idx] = fast_sigmoid(acc);
}

// ---------------------------------------------------------------------------
extern "C" void kernel_launch(void* const* d_in, const int* in_sizes, int n_in,
                              void* d_out, int out_size)
{
    const float* x      = (const float*)d_in[0];   // [16,256,128,128] f32
    const float* conv_w = (const float*)d_in[1];   // [1,2,3,3] f32
    float*       out    = (float*)d_out;           // [16,1,128,128] f32

    // Kernel 1: 8192 blocks x 256 threads (quarter-row quantum)
    reduce_mean_max_kernel<<<8192, 256>>>(x);

    // Kernel 2: 1024 blocks x 256 threads, PDL-overlapped launch
    cudaLaunchConfig_t cfg = {};
    cfg.gridDim  = dim3((B_ * HW_) / 256, 1, 1);
    cfg.blockDim = dim3(256, 1, 1);
    cfg.dynamicSmemBytes = 0;
    cfg.stream = 0;

    cudaLaunchAttribute attrs[1];
    attrs[0].id = cudaLaunchAttributeProgrammaticStreamSerialization;
    attrs[0].val.programmaticStreamSerializationAllowed = 1;
    cfg.attrs = attrs;
    cfg.numAttrs = 1;

    cudaLaunchKernelEx(&cfg, conv_sigmoid_kernel, conv_w, out);
}

// round 16
// speedup vs baseline: 1.0400x; 1.0400x over previous
#include <cuda_runtime.h>
#include <cuda_bf16.h>
#include <float.h>
#include <math.h>

// Problem shape (fixed by reference setup_inputs)
#define B_   16
#define C_   256
#define H_   128
#define W_   128
#define HW_  (H_ * W_)           // 16384
#define HW4_ (HW_ / 4)           // 4096 float4 columns per image
#define BHW_ (B_ * HW_)

// Q[kh][b][h][w]: 1-D conv contribution of feat row h (stored AT row h) with
// vertical tap kh. out[h] = Q0[h-1] + Q1[h] + Q2[h+1]. Unique writer per slot.
__device__ float g_Q[3 * BHW_];
// E[side][kh][b*H+rt]: boundary fixes for w=63 (side0) / w=64 (side1).
__device__ float g_E[2 * 3 * B_ * H_];

// MUFU-free sigmoid (R14): all FMA/ALU pipe.
__device__ __forceinline__ float fast_sigmoid(float x)
{
    float y = -x * 1.4426950408889634f;
    y = fminf(fmaxf(y, -126.0f), 126.0f);
    float n = floorf(y);
    float f = y - n;
    float p = 1.3333558146428443e-3f;
    p = fmaf(p, f, 9.8105352697968360e-3f);
    p = fmaf(p, f, 5.5518340325804030e-2f);
    p = fmaf(p, f, 2.4017933341410937e-1f);
    p = fmaf(p, f, 6.9314692312196549e-1f);
    p = fmaf(p, f, 1.0f);
    const float s = __int_as_float(((int)n + 127) << 23);
    const float t = s * p;                   // e^(-x)
    const float u = 1.0f + t;
    float r = __uint_as_float(0x7EF311C3u - __float_as_uint(u));
    r = r * (2.0f - u * r);
    r = r * (2.0f - u * r);
    r = r * (2.0f - u * r);
    return r;
}

// ---------------------------------------------------------------------------
// Kernel 1: R6 streaming body (4096 x 256, half-row x 16 splits, full unroll)
// + lean epilogue emitting the three 1-D conv row-contributions at row h.
// __launch_bounds__(256, 8) forces the 32-reg / 8-CTA fit (R13 regression fix).
// ---------------------------------------------------------------------------
__global__ __launch_bounds__(256, 8) void reduce_conv_rows_kernel(
    const float* __restrict__ x,
    const float* __restrict__ conv_w)   // [1,2,3,3] OIHW
{
    cudaTriggerProgrammaticLaunchCompletion();

    __shared__ float4 s_sum[256];
    __shared__ float4 s_max[256];
    __shared__ float  s_f[2][66];        // padded half-row: [ch][1+64+1]
    __shared__ float  s_w[18];

    const int tid  = threadIdx.x;
    const int col  = tid & 15;
    const int cs   = tid >> 4;

    const int blk    = blockIdx.x;             // 0..4095
    const int row_id = blk >> 1;
    const int half   = blk & 1;
    const int b      = row_id >> 7;
    const int h      = row_id & 127;
    const int hw4    = (h << 5) + (half << 4) + col;

    if (tid < 18) s_w[tid] = __ldg(conv_w + tid);

    const float4* xb = reinterpret_cast<const float4*>(x)
                     + (size_t)b * C_ * HW4_ + (size_t)(cs * 16) * HW4_ + hw4;

    float4 s = make_float4(0.f, 0.f, 0.f, 0.f);
    float4 m = make_float4(-FLT_MAX, -FLT_MAX, -FLT_MAX, -FLT_MAX);

    #pragma unroll
    for (int c = 0; c < 16; ++c) {
        float4 v = __ldcs(xb + (size_t)c * HW4_);
        s.x += v.x; s.y += v.y; s.z += v.z; s.w += v.w;
        m.x = fmaxf(m.x, v.x); m.y = fmaxf(m.y, v.y);
        m.z = fmaxf(m.z, v.z); m.w = fmaxf(m.w, v.w);
    }

    s_sum[tid] = s;
    s_max[tid] = m;
    __syncthreads();

    if (tid < 16) {
        #pragma unroll
        for (int k = 1; k < 16; ++k) {
            float4 ps = s_sum[tid + k * 16];
            float4 pm = s_max[tid + k * 16];
            s.x += ps.x; s.y += ps.y; s.z += ps.z; s.w += ps.w;
            m.x = fmaxf(m.x, pm.x); m.y = fmaxf(m.y, pm.y);
            m.z = fmaxf(m.z, pm.z); m.w = fmaxf(m.w, pm.w);
        }
        const float inv = 1.0f / (float)C_;
        s_f[0][1 + 4 * tid + 0] = s.x * inv;
        s_f[0][1 + 4 * tid + 1] = s.y * inv;
        s_f[0][1 + 4 * tid + 2] = s.z * inv;
        s_f[0][1 + 4 * tid + 3] = s.w * inv;
        s_f[1][1 + 4 * tid + 0] = m.x;
        s_f[1][1 + 4 * tid + 1] = m.y;
        s_f[1][1 + 4 * tid + 2] = m.z;
        s_f[1][1 + 4 * tid + 3] = m.w;
    }
    if (tid >= 16 && tid < 18) {     // tid 16,17 zero the pads
        s_f[tid - 16][0]  = 0.f;
        s_f[tid - 16][65] = 0.f;
    }
    __syncthreads();

    // Epilogue A: 64 threads, one output column each; stores at row h in all
    // three planes (fully coalesced, same address range).
    if (tid < 64) {
        float q0 = 0.f, q1 = 0.f, q2 = 0.f;
        #pragma unroll
        for (int kw = 0; kw < 3; ++kw) {
            const float f0 = s_f[0][tid + kw];
            const float f1 = s_f[1][tid + kw];
            q0 = fmaf(f0, s_w[0 * 3 + kw], fmaf(f1, s_w[9 + 0 * 3 + kw], q0));
            q1 = fmaf(f0, s_w[1 * 3 + kw], fmaf(f1, s_w[9 + 1 * 3 + kw], q1));
            q2 = fmaf(f0, s_w[2 * 3 + kw], fmaf(f1, s_w[9 + 2 * 3 + kw], q2));
        }
        const int base = b * HW_ + h * W_ + (half << 6) + tid;
        g_Q[0 * BHW_ + base] = q0;
        g_Q[1 * BHW_ + base] = q1;
        g_Q[2 * BHW_ + base] = q2;
    }

    // Epilogue B: boundary fix terms (one thread, 6 scalar stores).
    if (tid == 64) {
        const int side = 1 - half;   // half0 fixes w=64 (side1); half1 fixes w=63 (side0)
        const int kw   = (side == 0) ? 2 : 0;
        const int eidx = (side == 0) ? 1 : 64;
        const float e0 = s_f[0][eidx];
        const float e1 = s_f[1][eidx];
        #pragma unroll
        for (int kh = 0; kh < 3; ++kh) {
            const int rt = h + 1 - kh;
            if (rt < 0 || rt >= H_) continue;
            g_E[(side * 3 + kh) * B_ * H_ + b * H_ + rt] =
                e0 * s_w[kh * 3 + kw] + e1 * s_w[9 + kh * 3 + kw];
        }
    }
}

// ---------------------------------------------------------------------------
// Kernel 2: out = sigmoid(Q0[h-1]+Q1[h]+Q2[h+1] (+E at w=63/64)).
// 3 coalesced loads/px + MUFU-free sigmoid. 1024x256, PDL-overlapped.
// ---------------------------------------------------------------------------
__global__ __launch_bounds__(256) void sum_sigmoid_kernel(
    float* __restrict__ out)            // [B,1,H,W]
{
    cudaGridDependencySynchronize();

    const int idx = blockIdx.x * blockDim.x + threadIdx.x;  // 0 .. B*HW-1
    const int b  = idx >> 14;
    const int hw = idx & (HW_ - 1);
    const int h  = hw >> 7;
    const int w  = hw & (W_ - 1);

    const int rowbase = b * HW_ + h * W_ + w;
    float v = g_Q[1 * BHW_ + rowbase];
    if (h >= 1)      v += g_Q[0 * BHW_ + rowbase - W_];
    if (h <= H_ - 2) v += g_Q[2 * BHW_ + rowbase + W_];

    if (w == 63 || w == 64) {
        const int side = (w == 64);
        const int eb   = side * 3 * B_ * H_ + b * H_ + h;
        v += g_E[eb + 1 * B_ * H_];
        if (h >= 1)      v += g_E[eb + 0 * B_ * H_];
        if (h <= H_ - 2) v += g_E[eb + 2 * B_ * H_];
    }

    out[idx] = fast_sigmoid(v);
}

// ---------------------------------------------------------------------------
extern "C" void kernel_launch(void* const* d_in, const int* in_sizes, int n_in,
                              void* d_out, int out_size)
{
    const float* x      = (const float*)d_in[0];   // [16,256,128,128] f32
    const float* conv_w = (const float*)d_in[1];   // [1,2,3,3] f32
    float*       out    = (float*)d_out;           // [16,1,128,128] f32

    reduce_conv_rows_kernel<<<4096, 256>>>(x, conv_w);

    cudaLaunchConfig_t cfg = {};
    cfg.gridDim  = dim3((B_ * HW_) / 256, 1, 1);
    cfg.blockDim = dim3(256, 1, 1);
    cfg.dynamicSmemBytes = 0;
    cfg.stream = 0;

    cudaLaunchAttribute attrs[1];
    attrs[0].id = cudaLaunchAttributeProgrammaticStreamSerialization;
    attrs[0].val.programmaticStreamSerializationAllowed = 1;
    cfg.attrs = attrs;
    cfg.numAttrs = 1;

    cudaLaunchKernelEx(&cfg, sum_sigmoid_kernel, out);
}